// round 1
// baseline (speedup 1.0000x reference)
#include <cuda_runtime.h>
#include <cstdint>

// Problem constants
static constexpr int N_ = 1024;
static constexpr int K_ = 32;
static constexpr int I_ = 10000;
static constexpr int I4_ = I_ / 4;       // 2500 float4 chunks per row
static constexpr float EPS_ = 1e-10f;

__device__ __forceinline__ float lg2_approx(float v) {
    float r;
    asm("lg2.approx.f32 %0, %1;" : "=f"(r) : "f"(v));
    return r;
}
__device__ __forceinline__ float ex2_approx(float v) {
    float r;
    asm("ex2.approx.f32 %0, %1;" : "=f"(r) : "f"(v));
    return r;
}

// out[n,k] = (sum_i x[n,i] * w_i) / (sum_i w_i)
// w_i = exp2( 0.43280850*logits[k,i] - 0.1*log2( -ln2*log2(u+eps) + eps ) )
//   (base-2 rewrite of softmax((3*logits + gumbel)/10); A/B ratio cancels
//    the softmax normalization so no max-subtraction is required: the log2-
//    domain score lies in roughly [-0.6, +5.5], safe in fp32.)
__global__ void __launch_bounds__(1024, 1)
concrete_selector_kernel(const float* __restrict__ x,
                         const float* __restrict__ u,
                         const float* __restrict__ logits,
                         float* __restrict__ out) {
    __shared__ float xs[I_];   // 40000 B: x row for this n, reused by all 32 warps

    const int n   = blockIdx.x;
    const int tid = threadIdx.x;

    // Cooperative load of x[n, :] into shared (float4)
    {
        const float4* __restrict__ xg4 =
            reinterpret_cast<const float4*>(x + (size_t)n * I_);
        float4* xs4 = reinterpret_cast<float4*>(xs);
        for (int i = tid; i < I4_; i += 1024) xs4[i] = xg4[i];
    }
    __syncthreads();

    const int warp = tid >> 5;
    const int lane = tid & 31;
    const int k    = warp;    // 32 warps == 32 k's

    const float4* __restrict__ ug4 =
        reinterpret_cast<const float4*>(u + ((size_t)n * K_ + k) * (size_t)I_);
    const float4* __restrict__ cg4 =
        reinterpret_cast<const float4*>(logits + (size_t)k * I_);
    const float4* xs4 = reinterpret_cast<const float4*>(xs);

    float accA = 0.0f;   // sum x*w
    float accB = 0.0f;   // sum w

    auto body = [&](float uu, float lgv, float xv) {
        float l1    = lg2_approx(uu + EPS_);                  // log2(u+eps)      [MUFU]
        float inner = fmaf(l1, -0.69314718f, EPS_);           // -ln(u+eps)+eps   [FMA]
        float l2v   = lg2_approx(inner);                      //                  [MUFU]
        float s2    = fmaf(lgv, 0.43280850f, -0.1f * l2v);    // log2-score       [FMA x2]
        float w     = ex2_approx(s2);                         //                  [MUFU]
        accB += w;
        accA  = fmaf(xv, w, accA);
    };

    constexpr int MAIN = (I4_ / 32) * 32;   // 2496: uniform main loop
    #pragma unroll 2
    for (int j = lane; j < MAIN; j += 32) {
        float4 uu = __ldcs(&ug4[j]);   // streaming, evict-first: protect L2 for logits
        float4 cc = cg4[j];
        float4 xv = xs4[j];
        body(uu.x, cc.x, xv.x);
        body(uu.y, cc.y, xv.y);
        body(uu.z, cc.z, xv.z);
        body(uu.w, cc.w, xv.w);
    }
    // Tail: chunks 2496..2499 handled by lanes 0..3
    if (lane < I4_ - MAIN) {
        int j = MAIN + lane;
        float4 uu = __ldcs(&ug4[j]);
        float4 cc = cg4[j];
        float4 xv = xs4[j];
        body(uu.x, cc.x, xv.x);
        body(uu.y, cc.y, xv.y);
        body(uu.z, cc.z, xv.z);
        body(uu.w, cc.w, xv.w);
    }

    // Warp reduction (each warp owns its own (n,k))
    #pragma unroll
    for (int off = 16; off > 0; off >>= 1) {
        accA += __shfl_down_sync(0xffffffffu, accA, off);
        accB += __shfl_down_sync(0xffffffffu, accB, off);
    }
    if (lane == 0) {
        out[(size_t)n * K_ + k] = accA / accB;
    }
}

extern "C" void kernel_launch(void* const* d_in, const int* in_sizes, int n_in,
                              void* d_out, int out_size) {
    const float* x      = (const float*)d_in[0];   // (1024, 10000)
    const float* u      = (const float*)d_in[1];   // (1024, 32, 10000)
    const float* logits = (const float*)d_in[2];   // (32, 10000)
    float* out = (float*)d_out;                    // (1024, 32)
    (void)in_sizes; (void)n_in; (void)out_size;

    concrete_selector_kernel<<<N_, 1024>>>(x, u, logits, out);
}